// round 5
// baseline (speedup 1.0000x reference)
#include <cuda_runtime.h>
#include <cstdint>

// Problem constants
#define Bsz 32
#define Lsz 4096
#define Isz 128
#define Hsz 256
#define Osz 128
#define NDELAY 5      // delay line length (DELAY+1)

// Scratch (static device globals: allocation-free per harness rules)
// 3 x 128 MB
__device__ float g_xz[Bsz * Lsz * Hsz];
__device__ float g_xh[Bsz * Lsz * Hsz];
__device__ float g_hs[Bsz * Lsz * Hsz];

// ---------------------------------------------------------------------------
// Generic fp32 tiled GEMM with bias: C[M,N] = A[M,K] @ B[K,N] + bias[N]
// 64x64 tile per block, 256 threads, 4x4 micro-tile, K in chunks of 64.
// M,K,N all multiples of 64 here.
// ---------------------------------------------------------------------------
__global__ void __launch_bounds__(256) gemm_bias(
    const float* __restrict__ A, const float* __restrict__ Bm,
    const float* __restrict__ bias, float* __restrict__ C,
    int M, int K, int N)
{
    __shared__ float sA[64][68];   // pad 68: keeps float4 stores 16B-aligned
    __shared__ float sB[64][68];

    const int m0  = blockIdx.x << 6;
    const int n0  = blockIdx.y << 6;
    const int tid = threadIdx.x;
    const int tx  = tid & 15;
    const int ty  = tid >> 4;

    float acc[4][4];
#pragma unroll
    for (int i = 0; i < 4; i++)
#pragma unroll
        for (int j = 0; j < 4; j++) acc[i][j] = 0.f;

    for (int kk = 0; kk < K; kk += 64) {
#pragma unroll
        for (int i = 0; i < 4; i++) {
            int lin = tid + (i << 8);
            int r   = lin >> 4;
            int c   = (lin & 15) << 2;
            *(float4*)&sA[r][c] = *(const float4*)&A[(size_t)(m0 + r) * K + kk + c];
            *(float4*)&sB[r][c] = *(const float4*)&Bm[(size_t)(kk + r) * N + n0 + c];
        }
        __syncthreads();

#pragma unroll 16
        for (int k = 0; k < 64; k++) {
            float a0 = sA[(ty << 2) + 0][k];
            float a1 = sA[(ty << 2) + 1][k];
            float a2 = sA[(ty << 2) + 2][k];
            float a3 = sA[(ty << 2) + 3][k];
            float4 bv = *(float4*)&sB[k][tx << 2];
            acc[0][0] += a0 * bv.x; acc[0][1] += a0 * bv.y;
            acc[0][2] += a0 * bv.z; acc[0][3] += a0 * bv.w;
            acc[1][0] += a1 * bv.x; acc[1][1] += a1 * bv.y;
            acc[1][2] += a1 * bv.z; acc[1][3] += a1 * bv.w;
            acc[2][0] += a2 * bv.x; acc[2][1] += a2 * bv.y;
            acc[2][2] += a2 * bv.z; acc[2][3] += a2 * bv.w;
            acc[3][0] += a3 * bv.x; acc[3][1] += a3 * bv.y;
            acc[3][2] += a3 * bv.z; acc[3][3] += a3 * bv.w;
        }
        __syncthreads();
    }

    float4 bb = *(const float4*)&bias[n0 + (tx << 2)];
#pragma unroll
    for (int i = 0; i < 4; i++) {
        float4 o;
        o.x = acc[i][0] + bb.x;
        o.y = acc[i][1] + bb.y;
        o.z = acc[i][2] + bb.z;
        o.w = acc[i][3] + bb.w;
        *(float4*)&C[(size_t)(m0 + (ty << 2) + i) * N + n0 + (tx << 2)] = o;
    }
}

// ---------------------------------------------------------------------------
// Sequential MGRU scan.
//
// Grid: 128 CTAs = 32 clusters of 4 (one cluster per batch row).
// Each CTA owns 64 hidden columns; its Uz/Uh column slices live in REGISTERS
// (64+64 floats/thread over 256 threads = the CTA's 128KB weight quarter).
//
// Per step t (single cluster barrier, double-buffered `a` exchange):
//   B: a_j = z_j(t) * h_j(t-1)   (local), push a-chunk to all 4 CTAs' abuf[t&1]
//   C: barrier.cluster.arrive    (release: pushes visible after peers' wait)
//   D: overlap — compute z(t+1) from hist[(t+1)%5] (= h(t-4), already present)
//      and prefetch xz/xh(t+2) from gmem
//   E: barrier.cluster.wait      (acquire)
//   F: h~_j = tanh(xh + a_full . Uh[:,j]);  h_j = h + z*(h~ - h)
//   G: push h_j into hist[t%5] of all 4 CTAs (consumed at t+5 — 4 steps of
//      slack, ordered by intervening barriers); store h to gmem hs.
//
// Race freedom: reads of hist[t%5] (phase of step t, via z-compute) happen
// before arrive(t); writes to it happen after wait(t). abuf is parity
// double-buffered so one barrier/step suffices.
// ---------------------------------------------------------------------------
__device__ __forceinline__ void st_cluster_f32(uint32_t saddr, int rank, float v)
{
    uint32_t ra;
    asm volatile("mapa.shared::cluster.u32 %0, %1, %2;"
                 : "=r"(ra) : "r"(saddr), "r"(rank));
    asm volatile("st.shared::cluster.f32 [%0], %1;"
                 :: "r"(ra), "f"(v) : "memory");
}

__global__ void __launch_bounds__(256, 1) __cluster_dims__(4, 1, 1)
mgru_scan(const float* __restrict__ xz, const float* __restrict__ xh,
          const float* __restrict__ Uz, const float* __restrict__ Uh,
          float* __restrict__ hs)
{
    __shared__ __align__(16) float hist[NDELAY][Hsz];  // full h delay ring
    __shared__ __align__(16) float abuf[2][Hsz];       // a = z*h exchange, 2-buf

    const int rank = blockIdx.x & 3;   // cluster_ctarank (cluster_dims = 4,1,1)
    const int b    = blockIdx.x >> 2;  // batch row
    const int tid  = threadIdx.x;
    const int w    = tid >> 5;
    const int lane = tid & 31;
    const int ks   = lane & 3;         // K-slice id (4 slices of 64)
    const int cw   = lane >> 2;        // column-within-warp (8 cols/warp)
    const int jglob = rank * 64 + w * 8 + cw;   // global hidden column 0..255

    // Register-resident weight column slices
    float wz[64], wh[64];
    {
        const float* uz = Uz + (size_t)(ks * 64) * Hsz + jglob;
        const float* uh = Uh + (size_t)(ks * 64) * Hsz + jglob;
#pragma unroll
        for (int i = 0; i < 64; i++) {
            wz[i] = uz[(size_t)i * Hsz];
            wh[i] = uh[(size_t)i * Hsz];
        }
    }

    for (int i = tid; i < NDELAY * Hsz; i += 256) (&hist[0][0])[i] = 0.f;
    __syncthreads();

    const uint32_t hist_sa = (uint32_t)__cvta_generic_to_shared(&hist[0][0]);
    const uint32_t abuf_sa = (uint32_t)__cvta_generic_to_shared(&abuf[0][0]);

    const float* xzp = xz + (size_t)b * Lsz * Hsz + jglob;
    const float* xhp = xh + (size_t)b * Lsz * Hsz + jglob;
    float*       hsp = hs + (size_t)b * Lsz * Hsz + jglob;

    float h = 0.f;
    float xz_t = xzp[0];
    float xh_t = xhp[0];
    float xz_n = xzp[Hsz];
    float xh_n = xhp[Hsz];
    // z(0): hist is all zeros -> z = sigmoid(xz_0)
    float z = 1.f / (1.f + __expf(-xz_t));

    int s_cur = 0;   // t % 5
    int s_nxt = 1;   // (t+1) % 5

    for (int t = 0; t < Lsz; ++t) {
        // --- B: push a = z * h(t-1) into everyone's abuf[t&1] -------------
        float a = z * h;
        st_cluster_f32(abuf_sa + (uint32_t)(((t & 1) * Hsz + jglob) << 2), ks, a);
        asm volatile("barrier.cluster.arrive.aligned;" ::: "memory");

        // --- D: overlap barrier wait with z(t+1) + gmem prefetch ----------
        float zn;
        {
            const float4* hd = (const float4*)&hist[s_nxt][ks * 64];
            float s0 = 0.f, s1 = 0.f, s2 = 0.f, s3 = 0.f;
#pragma unroll
            for (int i = 0; i < 16; i++) {
                float4 v = hd[i];
                s0 += v.x * wz[4 * i + 0];
                s1 += v.y * wz[4 * i + 1];
                s2 += v.z * wz[4 * i + 2];
                s3 += v.w * wz[4 * i + 3];
            }
            float s = (s0 + s1) + (s2 + s3);
            s += __shfl_xor_sync(0xffffffffu, s, 1);
            s += __shfl_xor_sync(0xffffffffu, s, 2);
            zn = 1.f / (1.f + __expf(-(s + xz_n)));
        }
        float xz_p2 = 0.f, xh_p2 = 0.f;
        if (t + 2 < Lsz) {
            xz_p2 = __ldg(xzp + (size_t)(t + 2) * Hsz);
            xh_p2 = __ldg(xhp + (size_t)(t + 2) * Hsz);
        }

        asm volatile("barrier.cluster.wait.aligned;" ::: "memory");

        // --- F: candidate + state update ----------------------------------
        {
            const float4* av = (const float4*)&abuf[t & 1][ks * 64];
            float s0 = 0.f, s1 = 0.f, s2 = 0.f, s3 = 0.f;
#pragma unroll
            for (int i = 0; i < 16; i++) {
                float4 v = av[i];
                s0 += v.x * wh[4 * i + 0];
                s1 += v.y * wh[4 * i + 1];
                s2 += v.z * wh[4 * i + 2];
                s3 += v.w * wh[4 * i + 3];
            }
            float s = (s0 + s1) + (s2 + s3);
            s += __shfl_xor_sync(0xffffffffu, s, 1);
            s += __shfl_xor_sync(0xffffffffu, s, 2);
            float ht = tanhf(s + xh_t);
            h = h + z * (ht - h);   // (1-z)*h + z*ht
        }

        // --- G: broadcast h(t) into hist slot t%5 (read at t+5); store hs -
        st_cluster_f32(hist_sa + (uint32_t)((s_cur * Hsz + jglob) << 2), ks, h);
        if (ks == 0) hsp[(size_t)t * Hsz] = h;

        // rotate
        z = zn;
        xz_t = xz_n; xh_t = xh_n;
        xz_n = xz_p2; xh_n = xh_p2;
        s_cur = s_nxt;
        s_nxt = (s_nxt == NDELAY - 1) ? 0 : s_nxt + 1;
    }

    // No CTA may exit while a peer's DSMEM store targeting it is in flight.
    asm volatile("barrier.cluster.arrive.aligned;" ::: "memory");
    asm volatile("barrier.cluster.wait.aligned;" ::: "memory");
}

// ---------------------------------------------------------------------------
// Launch: xz/xh projections (2 GEMMs) -> scan -> head GEMM
// ---------------------------------------------------------------------------
extern "C" void kernel_launch(void* const* d_in, const int* in_sizes, int n_in,
                              void* d_out, int out_size)
{
    const float* x  = (const float*)d_in[0];
    const float* Wz = (const float*)d_in[1];
    const float* Uz = (const float*)d_in[2];
    const float* bz = (const float*)d_in[3];
    const float* Wh = (const float*)d_in[4];
    const float* Uh = (const float*)d_in[5];
    const float* bh = (const float*)d_in[6];
    const float* Wo = (const float*)d_in[7];
    const float* bo = (const float*)d_in[8];
    float* y = (float*)d_out;

    float *xz_p = nullptr, *xh_p = nullptr, *hs_p = nullptr;
    cudaGetSymbolAddress((void**)&xz_p, g_xz);
    cudaGetSymbolAddress((void**)&xh_p, g_xh);
    cudaGetSymbolAddress((void**)&hs_p, g_hs);

    const int M = Bsz * Lsz;           // 131072
    dim3 blk(256);

    // xz = x @ Wz + bz ; xh = x @ Wh + bh      [131072,128]@[128,256]
    gemm_bias<<<dim3(M / 64, Hsz / 64), blk>>>(x, Wz, bz, xz_p, M, Isz, Hsz);
    gemm_bias<<<dim3(M / 64, Hsz / 64), blk>>>(x, Wh, bh, xh_p, M, Isz, Hsz);

    // sequential scan: 32 clusters x 4 CTAs
    mgru_scan<<<Bsz * 4, 256>>>(xz_p, xh_p, Uz, Uh, hs_p);

    // y = hs @ Wo + bo                          [131072,256]@[256,128]
    gemm_bias<<<dim3(M / 64, Osz / 64), blk>>>(hs_p, Wo, bo, y, M, Hsz, Osz);
}

// round 6
// speedup vs baseline: 1.0034x; 1.0034x over previous
#include <cuda_runtime.h>
#include <cstdint>

// Problem constants
#define Bsz 32
#define Lsz 4096
#define Isz 128
#define Hsz 256
#define Osz 128
#define NDELAY 5      // delay line length (DELAY+1)

// Scratch (static device globals: allocation-free per harness rules)
__device__ float g_xz[Bsz * Lsz * Hsz];
__device__ float g_xh[Bsz * Lsz * Hsz];
__device__ float g_hs[Bsz * Lsz * Hsz];

// ---------------------------------------------------------------------------
// Generic fp32 tiled GEMM with bias: C[M,N] = A[M,K] @ B[K,N] + bias[N]
// 64x64 tile per block, 256 threads, 4x4 micro-tile, K in chunks of 64.
// ---------------------------------------------------------------------------
__global__ void __launch_bounds__(256) gemm_bias(
    const float* __restrict__ A, const float* __restrict__ Bm,
    const float* __restrict__ bias, float* __restrict__ C,
    int M, int K, int N)
{
    __shared__ float sA[64][68];
    __shared__ float sB[64][68];

    const int m0  = blockIdx.x << 6;
    const int n0  = blockIdx.y << 6;
    const int tid = threadIdx.x;
    const int tx  = tid & 15;
    const int ty  = tid >> 4;

    float acc[4][4];
#pragma unroll
    for (int i = 0; i < 4; i++)
#pragma unroll
        for (int j = 0; j < 4; j++) acc[i][j] = 0.f;

    for (int kk = 0; kk < K; kk += 64) {
#pragma unroll
        for (int i = 0; i < 4; i++) {
            int lin = tid + (i << 8);
            int r   = lin >> 4;
            int c   = (lin & 15) << 2;
            *(float4*)&sA[r][c] = *(const float4*)&A[(size_t)(m0 + r) * K + kk + c];
            *(float4*)&sB[r][c] = *(const float4*)&Bm[(size_t)(kk + r) * N + n0 + c];
        }
        __syncthreads();

#pragma unroll 16
        for (int k = 0; k < 64; k++) {
            float a0 = sA[(ty << 2) + 0][k];
            float a1 = sA[(ty << 2) + 1][k];
            float a2 = sA[(ty << 2) + 2][k];
            float a3 = sA[(ty << 2) + 3][k];
            float4 bv = *(float4*)&sB[k][tx << 2];
            acc[0][0] += a0 * bv.x; acc[0][1] += a0 * bv.y;
            acc[0][2] += a0 * bv.z; acc[0][3] += a0 * bv.w;
            acc[1][0] += a1 * bv.x; acc[1][1] += a1 * bv.y;
            acc[1][2] += a1 * bv.z; acc[1][3] += a1 * bv.w;
            acc[2][0] += a2 * bv.x; acc[2][1] += a2 * bv.y;
            acc[2][2] += a2 * bv.z; acc[2][3] += a2 * bv.w;
            acc[3][0] += a3 * bv.x; acc[3][1] += a3 * bv.y;
            acc[3][2] += a3 * bv.z; acc[3][3] += a3 * bv.w;
        }
        __syncthreads();
    }

    float4 bb = *(const float4*)&bias[n0 + (tx << 2)];
#pragma unroll
    for (int i = 0; i < 4; i++) {
        float4 o;
        o.x = acc[i][0] + bb.x;
        o.y = acc[i][1] + bb.y;
        o.z = acc[i][2] + bb.z;
        o.w = acc[i][3] + bb.w;
        *(float4*)&C[(size_t)(m0 + (ty << 2) + i) * N + n0 + (tx << 2)] = o;
    }
}

// ---------------------------------------------------------------------------
// Fast-math helpers (ex2/rcp approx: rel err ~1e-7, safe within 1e-3 budget)
// ---------------------------------------------------------------------------
__device__ __forceinline__ float ex2_fast(float x) {
    float r; asm("ex2.approx.f32 %0, %1;" : "=f"(r) : "f"(x)); return r;
}
__device__ __forceinline__ float rcp_fast(float x) {
    float r; asm("rcp.approx.f32 %0, %1;" : "=f"(r) : "f"(x)); return r;
}
__device__ __forceinline__ float sigmoid_fast(float x) {
    // 1/(1+e^-x) = 1/(1+2^(-x*log2e))
    return rcp_fast(1.f + ex2_fast(-1.4426950408889634f * x));
}
__device__ __forceinline__ float tanh_fast(float x) {
    // (e^2x - 1)/(e^2x + 1)
    float e = ex2_fast(2.885390081777927f * x);
    return (e - 1.f) * rcp_fast(e + 1.f);
}

// Packed f32x2 dot: 64 floats (16B-aligned shared ptr) . 32 packed weight pairs
__device__ __forceinline__ float dot64_f32x2(const float* p, const uint64_t* w) {
    const ulonglong2* v = (const ulonglong2*)p;
    uint64_t a0 = 0, a1 = 0, a2 = 0, a3 = 0;
#pragma unroll
    for (int i = 0; i < 8; i++) {
        ulonglong2 t = v[i];
        asm("fma.rn.f32x2 %0, %1, %2, %0;" : "+l"(a0) : "l"(t.x), "l"(w[2*i]));
        asm("fma.rn.f32x2 %0, %1, %2, %0;" : "+l"(a1) : "l"(t.y), "l"(w[2*i+1]));
    }
#pragma unroll
    for (int i = 8; i < 16; i++) {
        ulonglong2 t = v[i];
        asm("fma.rn.f32x2 %0, %1, %2, %0;" : "+l"(a2) : "l"(t.x), "l"(w[2*i]));
        asm("fma.rn.f32x2 %0, %1, %2, %0;" : "+l"(a3) : "l"(t.y), "l"(w[2*i+1]));
    }
    uint64_t s01, s23, s;
    asm("add.rn.f32x2 %0, %1, %2;" : "=l"(s01) : "l"(a0), "l"(a1));
    asm("add.rn.f32x2 %0, %1, %2;" : "=l"(s23) : "l"(a2), "l"(a3));
    asm("add.rn.f32x2 %0, %1, %2;" : "=l"(s)   : "l"(s01), "l"(s23));
    float lo, hi;
    asm("mov.b64 {%0, %1}, %2;" : "=f"(lo), "=f"(hi) : "l"(s));
    return lo + hi;
}

__device__ __forceinline__ void st_remote_f32(uint32_t addr, float v) {
    asm volatile("st.shared::cluster.f32 [%0], %1;" :: "r"(addr), "f"(v) : "memory");
}
__device__ __forceinline__ uint64_t pack2(float lo, float hi) {
    uint64_t r; asm("mov.b64 %0, {%1, %2};" : "=l"(r) : "f"(lo), "f"(hi)); return r;
}

// ---------------------------------------------------------------------------
// Sequential MGRU scan. 32 clusters x 4 CTAs, one cluster per batch row.
// Each CTA owns 64 hidden columns; Uz/Uh column slices live in registers,
// packed as f32x2 pairs. One cluster barrier per step; the barrier shadow
// (between arrive and wait) holds: z(t+1) dot from the delayed state,
// the hist DSMEM push of h(t-1), the hs STG, and the gmem prefetch.
//
// Slot protocol (all verified against barrier ordering):
//   abuf[(t)&1]     : a(t)=z(t)*h(t-1); written before arrive(t) (end of iter
//                     t-1 / prologue), read after wait(t).
//   hist[s%5]       : h(s); written in shadow of iter s+1, read in shadow of
//                     iter s+4 (z(s+5) needs h(s)); >=2 barriers of slack both
//                     directions.
// ---------------------------------------------------------------------------
__global__ void __launch_bounds__(256, 1) __cluster_dims__(4, 1, 1)
mgru_scan(const float* __restrict__ xz, const float* __restrict__ xh,
          const float* __restrict__ Uz, const float* __restrict__ Uh,
          float* __restrict__ hs)
{
    __shared__ __align__(16) float pool[(NDELAY + 2) * Hsz];
    float* hist = pool;                       // [5][256]
    const int ABUF = NDELAY * Hsz;            // abuf[2][256] after hist

    const int rank = blockIdx.x & 3;
    const int b    = blockIdx.x >> 2;
    const int tid  = threadIdx.x;
    const int w    = tid >> 5;
    const int lane = tid & 31;
    const int ks   = lane & 3;                // K-slice id (4 slices of 64)
    const int cw   = lane >> 2;               // col-within-warp
    const int jglob = rank * 64 + w * 8 + cw; // global hidden column

    // Register-resident packed weight slices (64 K-values -> 32 f32x2 pairs)
    uint64_t wz2[32], wh2[32];
    {
        const float* uz = Uz + (size_t)(ks * 64) * Hsz + jglob;
        const float* uh = Uh + (size_t)(ks * 64) * Hsz + jglob;
#pragma unroll
        for (int i = 0; i < 32; i++) {
            wz2[i] = pack2(uz[(size_t)(2*i) * Hsz], uz[(size_t)(2*i+1) * Hsz]);
            wh2[i] = pack2(uh[(size_t)(2*i) * Hsz], uh[(size_t)(2*i+1) * Hsz]);
        }
    }

    for (int i = tid; i < (NDELAY + 2) * Hsz; i += 256) pool[i] = 0.f;
    __syncthreads();

    uint32_t pool_sa = (uint32_t)__cvta_generic_to_shared(pool);
    uint32_t peer;   // base of pool in rank ks's SMEM (hoisted mapa)
    asm("mapa.shared::cluster.u32 %0, %1, %2;" : "=r"(peer) : "r"(pool_sa), "r"(ks));

    const float* xzp = xz + (size_t)b * Lsz * Hsz + jglob;
    const float* xhp = xh + (size_t)b * Lsz * Hsz + jglob;
    float*       hsp = hs + (size_t)b * Lsz * Hsz + jglob;

    float h      = 0.f;
    float xh_cur = xhp[0];
    float xz_nxt = xzp[Hsz];
    float xh_nxt = xhp[Hsz];
    float z      = sigmoid_fast(xzp[0]);   // z(0): delayed state is zero

    // Prologue: a(0) = z(0)*h(-1) = 0 -> abuf[0]; arrive(0)
    st_remote_f32(peer + (uint32_t)((ABUF + jglob) << 2), 0.f);
    asm volatile("barrier.cluster.arrive.aligned;" ::: "memory");

    int slot_r = 1;  // (t+1)%5 : read  h(t-4)
    int slot_w = 4;  // (t+4)%5 : write h(t-1)

    for (int t = 0; t < Lsz; ++t) {
        // ---- barrier shadow: z(t+1), hist push of h(t-1), hs STG, prefetch
        float s = dot64_f32x2(&hist[slot_r * Hsz + ks * 64], wz2);
        s += __shfl_xor_sync(0xffffffffu, s, 1);
        s += __shfl_xor_sync(0xffffffffu, s, 2);
        float zn = sigmoid_fast(s + xz_nxt);

        st_remote_f32(peer + (uint32_t)((slot_w * Hsz + jglob) << 2), h);
        if (ks == 0 && t > 0) hsp[(size_t)(t - 1) * Hsz] = h;

        float xz_p2 = 0.f, xh_p2 = 0.f;
        if (t + 2 < Lsz) {
            xz_p2 = __ldg(xzp + (size_t)(t + 2) * Hsz);
            xh_p2 = __ldg(xhp + (size_t)(t + 2) * Hsz);
        }

        asm volatile("barrier.cluster.wait.aligned;" ::: "memory");

        // ---- F: candidate + state update (uses a(t) from abuf[t&1])
        float sh = dot64_f32x2(&pool[ABUF + (t & 1) * Hsz + ks * 64], wh2);
        sh += __shfl_xor_sync(0xffffffffu, sh, 1);
        sh += __shfl_xor_sync(0xffffffffu, sh, 2);
        float ht = tanh_fast(sh + xh_cur);
        h = h + z * (ht - h);               // (1-z)*h + z*ht

        // ---- push a(t+1) = z(t+1)*h(t) into abuf[(t+1)&1]; arrive(t+1)
        st_remote_f32(peer + (uint32_t)((ABUF + ((t + 1) & 1) * Hsz + jglob) << 2),
                      zn * h);
        asm volatile("barrier.cluster.arrive.aligned;" ::: "memory");

        z = zn;
        xh_cur = xh_nxt;
        xz_nxt = xz_p2;
        xh_nxt = xh_p2;
        slot_r = (slot_r == NDELAY - 1) ? 0 : slot_r + 1;
        slot_w = (slot_w == NDELAY - 1) ? 0 : slot_w + 1;
    }

    if (ks == 0) hsp[(size_t)(Lsz - 1) * Hsz] = h;
    // match final arrive; also guarantees no CTA exits with peer stores inflight
    asm volatile("barrier.cluster.wait.aligned;" ::: "memory");
}

// Empty kernels to position the scan at global launch #6 for ncu (-s 5 -c 1)
__global__ void dummy_k() {}

// ---------------------------------------------------------------------------
// Launch: proj GEMMs -> (3 dummies) -> scan -> head GEMM
// ---------------------------------------------------------------------------
extern "C" void kernel_launch(void* const* d_in, const int* in_sizes, int n_in,
                              void* d_out, int out_size)
{
    const float* x  = (const float*)d_in[0];
    const float* Wz = (const float*)d_in[1];
    const float* Uz = (const float*)d_in[2];
    const float* bz = (const float*)d_in[3];
    const float* Wh = (const float*)d_in[4];
    const float* Uh = (const float*)d_in[5];
    const float* bh = (const float*)d_in[6];
    const float* Wo = (const float*)d_in[7];
    const float* bo = (const float*)d_in[8];
    float* y = (float*)d_out;

    float *xz_p = nullptr, *xh_p = nullptr, *hs_p = nullptr;
    cudaGetSymbolAddress((void**)&xz_p, g_xz);
    cudaGetSymbolAddress((void**)&xh_p, g_xh);
    cudaGetSymbolAddress((void**)&hs_p, g_hs);

    const int M = Bsz * Lsz;           // 131072
    dim3 blk(256);

    gemm_bias<<<dim3(M / 64, Hsz / 64), blk>>>(x, Wz, bz, xz_p, M, Isz, Hsz);
    gemm_bias<<<dim3(M / 64, Hsz / 64), blk>>>(x, Wh, bh, xh_p, M, Isz, Hsz);

    dummy_k<<<1, 1>>>();
    dummy_k<<<1, 1>>>();
    dummy_k<<<1, 1>>>();

    mgru_scan<<<Bsz * 4, 256>>>(xz_p, xh_p, Uz, Uh, hs_p);

    gemm_bias<<<dim3(M / 64, Osz / 64), blk>>>(hs_p, Wo, bo, y, M, Hsz, Osz);
}

// round 7
// speedup vs baseline: 1.0592x; 1.0556x over previous
#include <cuda_runtime.h>
#include <cstdint>

// Problem constants
#define Bsz 32
#define Lsz 4096
#define Isz 128
#define Hsz 256
#define Osz 128
#define NDELAY 5      // delay line length (DELAY+1)

// Scratch (static device globals: allocation-free per harness rules)
__device__ float g_xz[Bsz * Lsz * Hsz];
__device__ float g_xh[Bsz * Lsz * Hsz];
__device__ float g_hs[Bsz * Lsz * Hsz];

// ---------------------------------------------------------------------------
// Generic fp32 tiled GEMM with bias: C[M,N] = A[M,K] @ B[K,N] + bias[N]
// 64x64 tile per block, 256 threads, 4x4 micro-tile, K in chunks of 64.
// ---------------------------------------------------------------------------
__global__ void __launch_bounds__(256) gemm_bias(
    const float* __restrict__ A, const float* __restrict__ Bm,
    const float* __restrict__ bias, float* __restrict__ C,
    int M, int K, int N)
{
    __shared__ float sA[64][68];
    __shared__ float sB[64][68];

    const int m0  = blockIdx.x << 6;
    const int n0  = blockIdx.y << 6;
    const int tid = threadIdx.x;
    const int tx  = tid & 15;
    const int ty  = tid >> 4;

    float acc[4][4];
#pragma unroll
    for (int i = 0; i < 4; i++)
#pragma unroll
        for (int j = 0; j < 4; j++) acc[i][j] = 0.f;

    for (int kk = 0; kk < K; kk += 64) {
#pragma unroll
        for (int i = 0; i < 4; i++) {
            int lin = tid + (i << 8);
            int r   = lin >> 4;
            int c   = (lin & 15) << 2;
            *(float4*)&sA[r][c] = *(const float4*)&A[(size_t)(m0 + r) * K + kk + c];
            *(float4*)&sB[r][c] = *(const float4*)&Bm[(size_t)(kk + r) * N + n0 + c];
        }
        __syncthreads();

#pragma unroll 16
        for (int k = 0; k < 64; k++) {
            float a0 = sA[(ty << 2) + 0][k];
            float a1 = sA[(ty << 2) + 1][k];
            float a2 = sA[(ty << 2) + 2][k];
            float a3 = sA[(ty << 2) + 3][k];
            float4 bv = *(float4*)&sB[k][tx << 2];
            acc[0][0] += a0 * bv.x; acc[0][1] += a0 * bv.y;
            acc[0][2] += a0 * bv.z; acc[0][3] += a0 * bv.w;
            acc[1][0] += a1 * bv.x; acc[1][1] += a1 * bv.y;
            acc[1][2] += a1 * bv.z; acc[1][3] += a1 * bv.w;
            acc[2][0] += a2 * bv.x; acc[2][1] += a2 * bv.y;
            acc[2][2] += a2 * bv.z; acc[2][3] += a2 * bv.w;
            acc[3][0] += a3 * bv.x; acc[3][1] += a3 * bv.y;
            acc[3][2] += a3 * bv.z; acc[3][3] += a3 * bv.w;
        }
        __syncthreads();
    }

    float4 bb = *(const float4*)&bias[n0 + (tx << 2)];
#pragma unroll
    for (int i = 0; i < 4; i++) {
        float4 o;
        o.x = acc[i][0] + bb.x;
        o.y = acc[i][1] + bb.y;
        o.z = acc[i][2] + bb.z;
        o.w = acc[i][3] + bb.w;
        *(float4*)&C[(size_t)(m0 + (ty << 2) + i) * N + n0 + (tx << 2)] = o;
    }
}

// ---------------------------------------------------------------------------
// Fast-math helpers (ex2/rcp approx: rel err ~1e-7)
// ---------------------------------------------------------------------------
__device__ __forceinline__ float ex2_fast(float x) {
    float r; asm("ex2.approx.f32 %0, %1;" : "=f"(r) : "f"(x)); return r;
}
__device__ __forceinline__ float rcp_fast(float x) {
    float r; asm("rcp.approx.f32 %0, %1;" : "=f"(r) : "f"(x)); return r;
}
__device__ __forceinline__ float sigmoid_fast(float x) {
    return rcp_fast(1.f + ex2_fast(-1.4426950408889634f * x));
}
__device__ __forceinline__ float tanh_fast(float x) {
    float e = ex2_fast(2.885390081777927f * x);
    return (e - 1.f) * rcp_fast(e + 1.f);
}

// Packed f32x2 dot: 64 floats (16B-aligned shared ptr) . 32 packed weight pairs
__device__ __forceinline__ float dot64_f32x2(const float* p, const uint64_t* w) {
    const ulonglong2* v = (const ulonglong2*)p;
    uint64_t a0 = 0, a1 = 0, a2 = 0, a3 = 0;
#pragma unroll
    for (int i = 0; i < 8; i++) {
        ulonglong2 t = v[i];
        asm("fma.rn.f32x2 %0, %1, %2, %0;" : "+l"(a0) : "l"(t.x), "l"(w[2*i]));
        asm("fma.rn.f32x2 %0, %1, %2, %0;" : "+l"(a1) : "l"(t.y), "l"(w[2*i+1]));
    }
#pragma unroll
    for (int i = 8; i < 16; i++) {
        ulonglong2 t = v[i];
        asm("fma.rn.f32x2 %0, %1, %2, %0;" : "+l"(a2) : "l"(t.x), "l"(w[2*i]));
        asm("fma.rn.f32x2 %0, %1, %2, %0;" : "+l"(a3) : "l"(t.y), "l"(w[2*i+1]));
    }
    uint64_t s01, s23, s;
    asm("add.rn.f32x2 %0, %1, %2;" : "=l"(s01) : "l"(a0), "l"(a1));
    asm("add.rn.f32x2 %0, %1, %2;" : "=l"(s23) : "l"(a2), "l"(a3));
    asm("add.rn.f32x2 %0, %1, %2;" : "=l"(s)   : "l"(s01), "l"(s23));
    float lo, hi;
    asm("mov.b64 {%0, %1}, %2;" : "=f"(lo), "=f"(hi) : "l"(s));
    return lo + hi;
}

__device__ __forceinline__ uint64_t pack2(float lo, float hi) {
    uint64_t r; asm("mov.b64 %0, {%1, %2};" : "=l"(r) : "f"(lo), "f"(hi)); return r;
}

// Async remote store carrying 4 tx-bytes to the destination-CTA mbarrier.
__device__ __forceinline__ void st_async_f32(uint32_t daddr, float v, uint32_t mbar) {
    asm volatile(
        "st.async.shared::cluster.mbarrier::complete_tx::bytes.f32 [%0], %1, [%2];"
        :: "r"(daddr), "f"(v), "r"(mbar) : "memory");
}

__device__ __forceinline__ void mbar_expect_tx(uint32_t mbar, uint32_t bytes) {
    asm volatile("mbarrier.arrive.expect_tx.shared.b64 _, [%0], %1;"
                 :: "r"(mbar), "r"(bytes) : "memory");
}

__device__ __forceinline__ void mbar_wait(uint32_t mbar, uint32_t parity) {
    asm volatile(
        "{\n\t"
        ".reg .pred P;\n\t"
        "WAIT_%=:\n\t"
        "mbarrier.try_wait.parity.acquire.cluster.shared::cta.b64 P, [%0], %1, 10000000;\n\t"
        "@!P bra WAIT_%=;\n\t"
        "}"
        :: "r"(mbar), "r"(parity) : "memory");
}

// ---------------------------------------------------------------------------
// Sequential MGRU scan — mbarrier/st.async lockstep (no cluster barrier).
//
// 32 clusters x 4 CTAs, one cluster per batch row. Each CTA owns 64 hidden
// columns; Uz/Uh column slices live in registers as f32x2 pairs.
//
// Per step t, each destination CTA's mb[t&1] expects 2048 tx-bytes:
//   - 1024 B: a(t) = z(t) * h(t-1), pushed at the END of step t-1 (prologue
//             for t=0) into abuf[t&1],
//   - 1024 B: hist h(t-1), pushed early in step t into hist[(t+4)%5].
// Producers can never run >1 step ahead (a(t+1) needs full h(t), which needs
// every CTA's step-t wait), so double-buffered abuf / 5-slot hist / per-phase
// tx accounting are race-free. Reads of hist slot (t+1)%5 before wait(t) are
// covered by wait(t-3). The only dangling async op, a(L), is skipped; a final
// cluster barrier protects CTA exit while peer stores may be in flight.
// ---------------------------------------------------------------------------
__global__ void __launch_bounds__(256, 1) __cluster_dims__(4, 1, 1)
mgru_scan(const float* __restrict__ xz, const float* __restrict__ xh,
          const float* __restrict__ Uz, const float* __restrict__ Uh,
          float* __restrict__ hs)
{
    __shared__ __align__(16) float pool[(NDELAY + 2) * Hsz];
    __shared__ __align__(8) unsigned long long mb[2];
    float* hist = pool;                       // [5][256]
    const int ABUF = NDELAY * Hsz;            // abuf[2][256] after hist

    const int rank = blockIdx.x & 3;
    const int b    = blockIdx.x >> 2;
    const int tid  = threadIdx.x;
    const int w    = tid >> 5;
    const int lane = tid & 31;
    const int ks   = lane & 3;                // K-slice id (4 slices of 64)
    const int cw   = lane >> 2;               // col-within-warp
    const int jglob = rank * 64 + w * 8 + cw; // global hidden column

    // Register-resident packed weight slices (64 K-values -> 32 f32x2 pairs)
    uint64_t wz2[32], wh2[32];
    {
        const float* uz = Uz + (size_t)(ks * 64) * Hsz + jglob;
        const float* uh = Uh + (size_t)(ks * 64) * Hsz + jglob;
#pragma unroll
        for (int i = 0; i < 32; i++) {
            wz2[i] = pack2(uz[(size_t)(2*i) * Hsz], uz[(size_t)(2*i+1) * Hsz]);
            wh2[i] = pack2(uh[(size_t)(2*i) * Hsz], uh[(size_t)(2*i+1) * Hsz]);
        }
    }

    if (tid == 0) {
        uint32_t m0 = (uint32_t)__cvta_generic_to_shared(&mb[0]);
        asm volatile("mbarrier.init.shared.b64 [%0], 1;" :: "r"(m0) : "memory");
        asm volatile("mbarrier.init.shared.b64 [%0], 1;" :: "r"(m0 + 8) : "memory");
    }
    for (int i = tid; i < (NDELAY + 2) * Hsz; i += 256) pool[i] = 0.f;
    __syncthreads();
    // one-time: all CTAs' mbarriers + zeroed pools visible before any st.async
    asm volatile("barrier.cluster.arrive.aligned;" ::: "memory");
    asm volatile("barrier.cluster.wait.aligned;" ::: "memory");

    const uint32_t pool_sa = (uint32_t)__cvta_generic_to_shared(pool);
    const uint32_t mb_sa   = (uint32_t)__cvta_generic_to_shared(&mb[0]);
    uint32_t peer_pool, peer_mb;   // addresses in rank `ks`'s SMEM (hoisted mapa)
    asm("mapa.shared::cluster.u32 %0, %1, %2;" : "=r"(peer_pool) : "r"(pool_sa), "r"(ks));
    asm("mapa.shared::cluster.u32 %0, %1, %2;" : "=r"(peer_mb)   : "r"(mb_sa),   "r"(ks));

    const float* xzp = xz + (size_t)b * Lsz * Hsz + jglob;
    const float* xhp = xh + (size_t)b * Lsz * Hsz + jglob;
    float*       hsp = hs + (size_t)b * Lsz * Hsz + jglob;

    float h      = 0.f;
    float xh_cur = xhp[0];
    float xz_nxt = xzp[Hsz];
    float xh_nxt = xhp[Hsz];
    float z      = sigmoid_fast(xzp[0]);   // z(0): delayed state is zero

    // Prologue: a(0) = z(0)*h(-1) = 0 into abuf[0], tx -> mb[0]
    st_async_f32(peer_pool + (uint32_t)((ABUF + jglob) << 2), 0.f, peer_mb);

    int slot_r = 1;  // (t+1)%5 : read  h(t-4)
    int slot_w = 4;  // (t+4)%5 : write h(t-1)

    for (int t = 0; t < Lsz; ++t) {
        const uint32_t boff = (uint32_t)((t & 1) << 3);

        // ---- z(t+1) from delayed state (local read, covered by wait(t-3))
        float s = dot64_f32x2(&hist[slot_r * Hsz + ks * 64], wz2);
        s += __shfl_xor_sync(0xffffffffu, s, 1);
        s += __shfl_xor_sync(0xffffffffu, s, 2);
        float zn = sigmoid_fast(s + xz_nxt);

        // ---- push hist h(t-1) (1024 B of this step's 2048 expected)
        st_async_f32(peer_pool + (uint32_t)((slot_w * Hsz + jglob) << 2), h,
                     peer_mb + boff);
        if (ks == 0 && t > 0) hsp[(size_t)(t - 1) * Hsz] = h;

        float xz_p2 = 0.f, xh_p2 = 0.f;
        if (t + 2 < Lsz) {
            xz_p2 = __ldg(xzp + (size_t)(t + 2) * Hsz);
            xh_p2 = __ldg(xhp + (size_t)(t + 2) * Hsz);
        }

        // ---- consume: expect 2048 B (a(t) + hist h(t-1)), wait parity
        if (tid == 0) mbar_expect_tx(mb_sa + boff, 2048u);
        mbar_wait(mb_sa + boff, (uint32_t)((t >> 1) & 1));

        // ---- candidate + state update (uses a(t) from abuf[t&1])
        float sh = dot64_f32x2(&pool[ABUF + (t & 1) * Hsz + ks * 64], wh2);
        sh += __shfl_xor_sync(0xffffffffu, sh, 1);
        sh += __shfl_xor_sync(0xffffffffu, sh, 2);
        float ht = tanh_fast(sh + xh_cur);
        h = h + z * (ht - h);               // (1-z)*h + z*ht

        // ---- push a(t+1) = z(t+1)*h(t) into abuf[(t+1)&1], tx -> mb[(t+1)&1]
        if (t + 1 < Lsz)
            st_async_f32(peer_pool + (uint32_t)((ABUF + ((t + 1) & 1) * Hsz + jglob) << 2),
                         zn * h, peer_mb + (uint32_t)(((t + 1) & 1) << 3));

        z = zn;
        xh_cur = xh_nxt;
        xz_nxt = xz_p2;
        xh_nxt = xh_p2;
        slot_r = (slot_r == NDELAY - 1) ? 0 : slot_r + 1;
        slot_w = (slot_w == NDELAY - 1) ? 0 : slot_w + 1;
    }

    if (ks == 0) hsp[(size_t)(Lsz - 1) * Hsz] = h;
    // no CTA may exit while peer stores targeting it may be in flight
    asm volatile("barrier.cluster.arrive.aligned;" ::: "memory");
    asm volatile("barrier.cluster.wait.aligned;" ::: "memory");
}

// Dummy to position the scan as our 4th launch (ncu captures the 6th global
// launch; two harness launches precede ours — evidence: R5 captured our 4th).
__global__ void dummy_k() {}

// ---------------------------------------------------------------------------
// Launch: proj GEMMs -> dummy -> scan -> head GEMM
// ---------------------------------------------------------------------------
extern "C" void kernel_launch(void* const* d_in, const int* in_sizes, int n_in,
                              void* d_out, int out_size)
{
    const float* x  = (const float*)d_in[0];
    const float* Wz = (const float*)d_in[1];
    const float* Uz = (const float*)d_in[2];
    const float* bz = (const float*)d_in[3];
    const float* Wh = (const float*)d_in[4];
    const float* Uh = (const float*)d_in[5];
    const float* bh = (const float*)d_in[6];
    const float* Wo = (const float*)d_in[7];
    const float* bo = (const float*)d_in[8];
    float* y = (float*)d_out;

    float *xz_p = nullptr, *xh_p = nullptr, *hs_p = nullptr;
    cudaGetSymbolAddress((void**)&xz_p, g_xz);
    cudaGetSymbolAddress((void**)&xh_p, g_xh);
    cudaGetSymbolAddress((void**)&hs_p, g_hs);

    const int M = Bsz * Lsz;           // 131072
    dim3 blk(256);

    gemm_bias<<<dim3(M / 64, Hsz / 64), blk>>>(x, Wz, bz, xz_p, M, Isz, Hsz);
    gemm_bias<<<dim3(M / 64, Hsz / 64), blk>>>(x, Wh, bh, xh_p, M, Isz, Hsz);

    dummy_k<<<1, 1>>>();

    mgru_scan<<<Bsz * 4, 256>>>(xz_p, xh_p, Uz, Uh, hs_p);

    gemm_bias<<<dim3(M / 64, Osz / 64), blk>>>(hs_p, Wo, bo, y, M, Hsz, Osz);
}